// round 15
// baseline (speedup 1.0000x reference)
#include <cuda_runtime.h>
#include <cuda_bf16.h>
#include <math.h>
#include <stdint.h>

// Problem constants
#define B_    32
#define N_    4096
#define F_    768
#define K_    8
#define D_    256
#define NB_   (B_ * N_)          // 131072 rows
#define NCHUNK 16                // token chunks of 256
#define SCALE_ 0.0625f           // 256^-0.5
#define EPS_   1e-8f

// ---------------- scratch (device globals; no allocation allowed) ----------
__device__ float g_fn[(size_t)NB_ * F_];        // LN(features) fp32 (402MB)
__device__ float g_qt[B_ * K_ * F_];            // q-tilde = q @ Wk  (B,8,768)
__device__ float g_slots[B_ * K_ * D_];
__device__ float g_partial[B_ * K_ * NCHUNK];
__device__ float g_rowsum[B_ * K_];
__device__ float g_upart[(size_t)B_ * NCHUNK * K_ * F_];  // U partials (12.6MB)
__device__ float g_WihT[768 * 256];
__device__ float g_WhhT[768 * 256];
__device__ float g_W1T[256 * 256];
__device__ float g_W2T[256 * 256];
__device__ float g_WqT[256 * 256];
__device__ float g_WvT[768 * 256];

// ---------------- fused LN of features -> fp32 g_fn ------------------------
__global__ void __launch_bounds__(256) ln_conv(const float* __restrict__ feat,
                                               const float* __restrict__ gin,
                                               const float* __restrict__ bin) {
    int row = blockIdx.x;
    const float* p = feat + (size_t)row * F_;
    int t = threadIdx.x;
    float x0 = p[t], x1 = p[t + 256], x2 = p[t + 512];
    float s  = x0 + x1 + x2;
    float ss = x0 * x0 + x1 * x1 + x2 * x2;
    __shared__ float r1[256], r2[256];
    r1[t] = s; r2[t] = ss;
    __syncthreads();
    for (int o = 128; o; o >>= 1) {
        if (t < o) { r1[t] += r1[t + o]; r2[t] += r2[t + o]; }
        __syncthreads();
    }
    float mean = r1[0] * (1.f / 768.f);
    float var  = r2[0] * (1.f / 768.f) - mean * mean;
    float rstd = rsqrtf(var + 1e-5f);
    float xs[3] = {x0, x1, x2};
    float* o = g_fn + (size_t)row * F_;
#pragma unroll
    for (int j = 0; j < 3; j++) {
        int idx = t + 256 * j;
        o[idx] = (xs[j] - mean) * rstd * gin[idx] + bin[idx];
    }
}

// ---------------- generic transpose into device-global targets ------------
__device__ __forceinline__ float* tgt_ptr(int sel) {
    switch (sel) {
        case 0: return g_WihT;
        case 1: return g_WhhT;
        case 2: return g_W1T;
        case 3: return g_W2T;
        case 4: return g_WqT;
        default: return g_WvT;
    }
}

__global__ void transpose_k(const float* __restrict__ src, int R, int C, int sel) {
    __shared__ float tile[32][33];
    float* dst = tgt_ptr(sel);
    int bx = blockIdx.x * 32, by = blockIdx.y * 32;
    int x = bx + threadIdx.x;
    for (int i = 0; i < 32; i += 8) {
        int y = by + threadIdx.y + i;
        if (y < R && x < C) tile[threadIdx.y + i][threadIdx.x] = src[(size_t)y * C + x];
    }
    __syncthreads();
    int x2 = by + threadIdx.x;
    for (int i = 0; i < 32; i += 8) {
        int y2 = bx + threadIdx.y + i;
        if (y2 < C && x2 < R) dst[(size_t)y2 * R + x2] = tile[threadIdx.x][threadIdx.y + i];
    }
}

// ---------------- slot init ------------------------------------------------
__global__ void __launch_bounds__(256) copy_slots(const float* __restrict__ prev) {
    int i = blockIdx.x * 256 + threadIdx.x;
    g_slots[i] = prev[i];
}

// ---------------- q projection + Wk folding --------------------------------
__global__ void __launch_bounds__(256) qproj_fold(const float* __restrict__ g_sw,
                                                  const float* __restrict__ b_sw,
                                                  const float* __restrict__ Wk) {
    int idx = blockIdx.x;  // b*8+k
    int t = threadIdx.x;
    __shared__ float r1[256], r2[256], lnv[256], qsm[256];
    float x = g_slots[idx * D_ + t];
    r1[t] = x; r2[t] = x * x;
    __syncthreads();
    for (int o = 128; o; o >>= 1) {
        if (t < o) { r1[t] += r1[t + o]; r2[t] += r2[t + o]; }
        __syncthreads();
    }
    float mean = r1[0] * (1.f / 256.f);
    float var  = r2[0] * (1.f / 256.f) - mean * mean;
    float rstd = rsqrtf(var + 1e-5f);
    __syncthreads();
    lnv[t] = (x - mean) * rstd * g_sw[t] + b_sw[t];
    __syncthreads();
    float acc = 0.f;
#pragma unroll 8
    for (int d = 0; d < 256; d++) acc += lnv[d] * g_WqT[d * 256 + t];
    qsm[t] = acc;
    __syncthreads();
    float a0 = 0.f, a1 = 0.f, a2 = 0.f;
#pragma unroll 4
    for (int h = 0; h < 256; h++) {
        float qh = qsm[h];
        const float* wr = Wk + (size_t)h * F_;
        a0 += qh * wr[t];
        a1 += qh * wr[t + 256];
        a2 += qh * wr[t + 512];
    }
    float* o = g_qt + (size_t)idx * F_;
    o[t] = a0; o[t + 256] = a1; o[t + 512] = a2;
}

// ---------------- fused attention pass -------------------------------------
// grid (NCHUNK=16, B=32), 256 threads.
// Phase 1 (token per thread): logits = q~ . fn * SCALE, softmax over 8 slots.
// Phase 2 (warp per 32-token group): U partials for all 8 slots; lanes = f-dims.
#define FCH 64                   // dims per tile chunk
#define NCH (F_ / FCH)           // 12
#define TROW 68                  // tile row stride (floats)
#define OFF_TILE 0
#define OFF_QT   (256 * TROW)                 // 17408 floats
#define OFF_RED  OFF_QT                       // overlay (phase2 only, 4096 floats)
#define OFF_ATT  (OFF_QT + K_ * F_)           // +6144
#define OFF_WS   (OFF_ATT + 256 * K_)         // +2048
#define SM_ATT_BYTES ((OFF_WS + 64) * 4)      // ~102.7 KB

__global__ void __launch_bounds__(256) fused_attn(float* __restrict__ attn_ext,
                                                  int final_pass) {
    extern __shared__ float sm[];
    int c = blockIdx.x, b = blockIdx.y;
    int t = threadIdx.x, w = t >> 5, lane = t & 31;
    float* tile = sm + OFF_TILE;
    float* qts  = sm + OFF_QT;
    float* red  = sm + OFF_RED;
    float* atT  = sm + OFF_ATT;
    float* ws   = sm + OFF_WS;

    // load q~ (8 x 768)
    const float4* qg = (const float4*)(g_qt + (size_t)b * K_ * F_);
#pragma unroll
    for (int i = 0; i < 6; i++) ((float4*)qts)[i * 256 + t] = qg[i * 256 + t];

    const float4* fg = (const float4*)(g_fn + ((size_t)(b * N_ + c * 256)) * F_);

    float acc[K_];
#pragma unroll
    for (int s = 0; s < K_; s++) acc[s] = 0.f;

    for (int ch = 0; ch < NCH; ch++) {
        __syncthreads();
#pragma unroll
        for (int i = 0; i < 16; i++) {
            int f = i * 256 + t;
            int r = f >> 4, dq = f & 15;
            float4 v = fg[(size_t)r * 192 + ch * 16 + dq];
            *(float4*)&tile[r * TROW + dq * 4] = v;
        }
        __syncthreads();
#pragma unroll
        for (int dq = 0; dq < 16; dq++) {
            float4 kv = *(float4*)&tile[t * TROW + dq * 4];
#pragma unroll
            for (int s = 0; s < K_; s++) {
                float4 qv = *(float4*)&qts[s * F_ + ch * FCH + dq * 4];
                acc[s] += kv.x * qv.x + kv.y * qv.y + kv.z * qv.z + kv.w * qv.w;
            }
        }
    }

    float mx = acc[0] * SCALE_;
#pragma unroll
    for (int s = 0; s < K_; s++) { acc[s] *= SCALE_; mx = fmaxf(mx, acc[s]); }
    float e[K_], den = 0.f;
#pragma unroll
    for (int s = 0; s < K_; s++) { e[s] = expf(acc[s] - mx); den += e[s]; }
    float inv = 1.f / den;
#pragma unroll
    for (int s = 0; s < K_; s++) e[s] *= inv;
    // transposed attn store: atT[tok][slot]
    *(float4*)&atT[t * K_]     = make_float4(e[0], e[1], e[2], e[3]);
    *(float4*)&atT[t * K_ + 4] = make_float4(e[4], e[5], e[6], e[7]);
    if (final_pass) {
        int n = c * 256 + t;
#pragma unroll
        for (int s = 0; s < K_; s++)
            attn_ext[((size_t)(b * K_ + s)) * N_ + n] = e[s];
    }
    // rowsum partials
#pragma unroll
    for (int s = 0; s < K_; s++) {
        float r = e[s];
#pragma unroll
        for (int off = 16; off; off >>= 1) r += __shfl_xor_sync(0xFFFFFFFFu, r, off);
        if (lane == 0) ws[w * K_ + s] = r;
    }
    __syncthreads();
    if (t < K_) {
        float smv = 0.f;
#pragma unroll
        for (int w2 = 0; w2 < 8; w2++) smv += ws[w2 * K_ + t];
        g_partial[(b * K_ + t) * NCHUNK + c] = smv;
    }

    if (!final_pass) {
        // phase 2: warp w owns tokens [w*32, w*32+32); lanes cover 64 f of chunk
        int wtok = w * 32;
        int sslot = t >> 5, f2 = (lane) * 2;  // for final reduce mapping
        for (int ch = 0; ch < NCH; ch++) {
            __syncthreads();
#pragma unroll
            for (int i = 0; i < 16; i++) {
                int f = i * 256 + t;
                int r = f >> 4, dq = f & 15;
                float4 v = fg[(size_t)r * 192 + ch * 16 + dq];
                *(float4*)&tile[r * TROW + dq * 4] = v;
            }
            __syncthreads();
            float u[16];
#pragma unroll
            for (int j = 0; j < 16; j++) u[j] = 0.f;
#pragma unroll 4
            for (int tk = 0; tk < 32; tk++) {
                int tok = wtok + tk;
                float2 fv = *(float2*)&tile[tok * TROW + lane * 2];
                float4 a0 = *(float4*)&atT[tok * K_];
                float4 a1 = *(float4*)&atT[tok * K_ + 4];
                u[0] += a0.x * fv.x;  u[1] += a0.x * fv.y;
                u[2] += a0.y * fv.x;  u[3] += a0.y * fv.y;
                u[4] += a0.z * fv.x;  u[5] += a0.z * fv.y;
                u[6] += a0.w * fv.x;  u[7] += a0.w * fv.y;
                u[8] += a1.x * fv.x;  u[9] += a1.x * fv.y;
                u[10] += a1.y * fv.x; u[11] += a1.y * fv.y;
                u[12] += a1.z * fv.x; u[13] += a1.z * fv.y;
                u[14] += a1.w * fv.x; u[15] += a1.w * fv.y;
            }
            // per-warp partials -> red[w][s][64]
#pragma unroll
            for (int s = 0; s < K_; s++)
                *(float2*)&red[(w * K_ + s) * FCH + lane * 2] = make_float2(u[2 * s], u[2 * s + 1]);
            __syncthreads();
            // cross-warp reduce: thread -> (slot = t>>5, f pair = lane*2)
            float r0 = 0.f, r1v = 0.f;
#pragma unroll
            for (int w2 = 0; w2 < 8; w2++) {
                float2 p = *(float2*)&red[(w2 * K_ + sslot) * FCH + f2];
                r0 += p.x; r1v += p.y;
            }
            float* up = g_upart + ((size_t)((b * NCHUNK + c) * K_ + sslot)) * F_ + ch * FCH + f2;
            *(float2*)up = make_float2(r0, r1v);
        }
    }
}

// ---------------- deterministic row-sum reduce -----------------------------
__global__ void __launch_bounds__(256) rowsum_reduce() {
    int t = threadIdx.x;  // 256 = B*K
    float s = 0.f;
#pragma unroll
    for (int c = 0; c < NCHUNK; c++) s += g_partial[t * NCHUNK + c];
    g_rowsum[t] = s;
}

// ---------------- U reduce + Wv fold + GRU + LN + MLP (per slot) -----------
__global__ void __launch_bounds__(256) gru_mlp(const float* __restrict__ b_ih,
                                               const float* __restrict__ b_hh,
                                               const float* __restrict__ g_mw,
                                               const float* __restrict__ b_mw,
                                               const float* __restrict__ b1,
                                               const float* __restrict__ b2) {
    int idx = blockIdx.x;  // b*8+k
    int b = idx >> 3, k = idx & 7;
    int t = threadIdx.x;
    __shared__ float us[768];
    __shared__ float upd[256], slt[256], lnbuf[256], mbuf[256], r1[256], r2[256];

#pragma unroll
    for (int j = 0; j < 3; j++) {
        int f = t + 256 * j;
        float s = 0.f;
#pragma unroll
        for (int c = 0; c < NCHUNK; c++)
            s += g_upart[((size_t)((b * NCHUNK + c) * K_ + k)) * F_ + f];
        us[f] = s;
    }
    float sv = g_slots[idx * D_ + t];
    slt[t] = sv;
    __syncthreads();

    float invr = 1.f / (g_rowsum[idx] + EPS_);
    float a = 0.f;
#pragma unroll 8
    for (int f = 0; f < 768; f++) a += us[f] * g_WvT[f * 256 + t];
    upd[t] = a * invr;
    __syncthreads();

    float gir = b_ih[t], giz = b_ih[256 + t], gin = b_ih[512 + t];
    float ghr = b_hh[t], ghz = b_hh[256 + t], ghn = b_hh[512 + t];
#pragma unroll 4
    for (int d = 0; d < 256; d++) {
        float ud = upd[d], sd = slt[d];
        const float* wi = &g_WihT[d * 768];
        const float* wh = &g_WhhT[d * 768];
        gir += ud * wi[t];       ghr += sd * wh[t];
        giz += ud * wi[256 + t]; ghz += sd * wh[256 + t];
        gin += ud * wi[512 + t]; ghn += sd * wh[512 + t];
    }
    float r = 1.f / (1.f + expf(-(gir + ghr)));
    float z = 1.f / (1.f + expf(-(giz + ghz)));
    float nn = tanhf(gin + r * ghn);
    float h = (1.f - z) * nn + z * sv;

    r1[t] = h; r2[t] = h * h;
    __syncthreads();
    for (int o = 128; o; o >>= 1) {
        if (t < o) { r1[t] += r1[t + o]; r2[t] += r2[t + o]; }
        __syncthreads();
    }
    float mean = r1[0] * (1.f / 256.f);
    float var  = r2[0] * (1.f / 256.f) - mean * mean;
    float rstd = rsqrtf(var + 1e-5f);
    __syncthreads();
    lnbuf[t] = (h - mean) * rstd * g_mw[t] + b_mw[t];
    __syncthreads();

    float acc = b1[t];
#pragma unroll 8
    for (int d = 0; d < 256; d++) acc += lnbuf[d] * g_W1T[d * 256 + t];
    mbuf[t] = fmaxf(acc, 0.f);
    __syncthreads();

    float o = h + b2[t];
#pragma unroll 8
    for (int j = 0; j < 256; j++) o += mbuf[j] * g_W2T[j * 256 + t];
    g_slots[idx * D_ + t] = o;
}

// ---------------- final confidence blend -----------------------------------
__global__ void __launch_bounds__(256) blend(const float* __restrict__ prev,
                                             float* __restrict__ out_slots) {
    int idx = blockIdx.x;  // b*8+k
    int t = threadIdx.x;
    float mask = 1.f / (1.f + expf(-g_rowsum[idx] * (1.f / (float)N_)));
    out_slots[idx * D_ + t] =
        g_slots[idx * D_ + t] * mask + prev[idx * D_ + t] * (1.f - mask);
}

// ---------------- launch ----------------------------------------------------
extern "C" void kernel_launch(void* const* d_in, const int* in_sizes, int n_in,
                              void* d_out, int out_size) {
    const float* features = (const float*)d_in[0];
    const float* prev_slots = (const float*)d_in[1];
    const float* gin  = (const float*)d_in[2];
    const float* bin  = (const float*)d_in[3];
    const float* g_sw = (const float*)d_in[4];
    const float* b_sw = (const float*)d_in[5];
    const float* g_mw = (const float*)d_in[6];
    const float* b_mw = (const float*)d_in[7];
    const float* Wq   = (const float*)d_in[8];
    const float* Wk   = (const float*)d_in[9];
    const float* Wv   = (const float*)d_in[10];
    const float* W_ih = (const float*)d_in[11];
    const float* W_hh = (const float*)d_in[12];
    const float* b_ih = (const float*)d_in[13];
    const float* b_hh = (const float*)d_in[14];
    const float* W1   = (const float*)d_in[15];
    const float* b1   = (const float*)d_in[16];
    const float* W2   = (const float*)d_in[17];
    const float* b2   = (const float*)d_in[18];

    float* out = (float*)d_out;
    float* out_slots = out;                       // (B, K, 256)
    float* out_attn  = out + B_ * K_ * D_;        // (B, K, N)

    cudaFuncSetAttribute(fused_attn, cudaFuncAttributeMaxDynamicSharedMemorySize,
                         SM_ATT_BYTES);

    // launch order arranged so ncu (-s 5 -c 1) profiles the first fused_attn
    ln_conv<<<NB_, 256>>>(features, gin, bin);                               // 0
    copy_slots<<<(B_ * K_ * D_) / 256, 256>>>(prev_slots);                   // 1
    transpose_k<<<dim3(256 / 32, 256 / 32), dim3(32, 8)>>>(Wq, 256, 256, 4); // 2
    qproj_fold<<<B_ * K_, 256>>>(g_sw, b_sw, Wk);                            // 3
    transpose_k<<<dim3(768 / 32, 256 / 32), dim3(32, 8)>>>(Wv, 256, 768, 5); // 4
    fused_attn<<<dim3(NCHUNK, B_), 256, SM_ATT_BYTES>>>(out_attn, 0);        // 5 <- profiled
    transpose_k<<<dim3(256 / 32, 768 / 32), dim3(32, 8)>>>(W_ih, 768, 256, 0);
    transpose_k<<<dim3(256 / 32, 768 / 32), dim3(32, 8)>>>(W_hh, 768, 256, 1);
    transpose_k<<<dim3(256 / 32, 256 / 32), dim3(32, 8)>>>(W1, 256, 256, 2);
    transpose_k<<<dim3(256 / 32, 256 / 32), dim3(32, 8)>>>(W2, 256, 256, 3);
    rowsum_reduce<<<1, 256>>>();
    gru_mlp<<<B_ * K_, 256>>>(b_ih, b_hh, g_mw, b_mw, b1, b2);

    for (int it = 1; it < 3; it++) {
        qproj_fold<<<B_ * K_, 256>>>(g_sw, b_sw, Wk);
        fused_attn<<<dim3(NCHUNK, B_), 256, SM_ATT_BYTES>>>(out_attn, 0);
        rowsum_reduce<<<1, 256>>>();
        gru_mlp<<<B_ * K_, 256>>>(b_ih, b_hh, g_mw, b_mw, b1, b2);
    }

    qproj_fold<<<B_ * K_, 256>>>(g_sw, b_sw, Wk);
    fused_attn<<<dim3(NCHUNK, B_), 256, SM_ATT_BYTES>>>(out_attn, 1);
    rowsum_reduce<<<1, 256>>>();
    blend<<<B_ * K_, 256>>>(prev_slots, out_slots);
}

// round 16
// speedup vs baseline: 1.0189x; 1.0189x over previous
#include <cuda_runtime.h>
#include <cuda_bf16.h>
#include <math.h>
#include <stdint.h>

// Problem constants
#define B_    32
#define N_    4096
#define F_    768
#define K_    8
#define D_    256
#define NB_   (B_ * N_)          // 131072 rows
#define NCHUNK 16                // token chunks of 256
#define SCALE_ 0.0625f           // 256^-0.5
#define EPS_   1e-8f

// ---------------- scratch (device globals; no allocation allowed) ----------
__device__ float g_fn[(size_t)NB_ * F_];        // LN(features) fp32 (402MB)
__device__ float g_qt[B_ * K_ * F_];            // q-tilde = LN(slots) @ M
__device__ float g_slots[B_ * K_ * D_];
__device__ float g_partial[B_ * K_ * NCHUNK];
__device__ float g_rowsum[B_ * K_];
__device__ float g_upart[(size_t)B_ * NCHUNK * K_ * F_];  // U partials (12.6MB)
__device__ float g_WihT[768 * 256];
__device__ float g_WhhT[768 * 256];
__device__ float g_W1T[256 * 256];
__device__ float g_W2T[256 * 256];
__device__ float g_WvT[768 * 256];
__device__ float g_M[256 * 768];      // M[d*768+f] = sum_h Wq[h,d]*Wk[h,f]

// ---------------- fused LN of features -> fp32 g_fn ------------------------
__global__ void __launch_bounds__(256) ln_conv(const float* __restrict__ feat,
                                               const float* __restrict__ gin,
                                               const float* __restrict__ bin) {
    int row = blockIdx.x;
    const float* p = feat + (size_t)row * F_;
    int t = threadIdx.x;
    float x0 = p[t], x1 = p[t + 256], x2 = p[t + 512];
    float s  = x0 + x1 + x2;
    float ss = x0 * x0 + x1 * x1 + x2 * x2;
    __shared__ float r1[256], r2[256];
    r1[t] = s; r2[t] = ss;
    __syncthreads();
    for (int o = 128; o; o >>= 1) {
        if (t < o) { r1[t] += r1[t + o]; r2[t] += r2[t + o]; }
        __syncthreads();
    }
    float mean = r1[0] * (1.f / 768.f);
    float var  = r2[0] * (1.f / 768.f) - mean * mean;
    float rstd = rsqrtf(var + 1e-5f);
    float xs[3] = {x0, x1, x2};
    float* o = g_fn + (size_t)row * F_;
#pragma unroll
    for (int j = 0; j < 3; j++) {
        int idx = t + 256 * j;
        o[idx] = (xs[j] - mean) * rstd * gin[idx] + bin[idx];
    }
}

// ---------------- M = Wq^T @ Wk  (256 x 768) --------------------------------
__global__ void __launch_bounds__(256) make_M(const float* __restrict__ Wq,
                                              const float* __restrict__ Wk) {
    int d = blockIdx.x;          // 0..255
    int t = threadIdx.x;
    __shared__ float wq[256];
    wq[t] = Wq[t * 256 + d];     // Wq[h=t, d]
    __syncthreads();
#pragma unroll
    for (int j = 0; j < 3; j++) {
        int f = t + 256 * j;
        float s0 = 0.f, s1 = 0.f;
#pragma unroll 4
        for (int h = 0; h < 256; h += 2) {
            s0 += wq[h]     * Wk[(size_t)h * 768 + f];
            s1 += wq[h + 1] * Wk[(size_t)(h + 1) * 768 + f];
        }
        g_M[(size_t)d * 768 + f] = s0 + s1;
    }
}

// ---------------- generic transpose into device-global targets ------------
__device__ __forceinline__ float* tgt_ptr(int sel) {
    switch (sel) {
        case 0: return g_WihT;
        case 1: return g_WhhT;
        case 2: return g_W1T;
        case 3: return g_W2T;
        default: return g_WvT;
    }
}

__global__ void transpose_k(const float* __restrict__ src, int R, int C, int sel) {
    __shared__ float tile[32][33];
    float* dst = tgt_ptr(sel);
    int bx = blockIdx.x * 32, by = blockIdx.y * 32;
    int x = bx + threadIdx.x;
    for (int i = 0; i < 32; i += 8) {
        int y = by + threadIdx.y + i;
        if (y < R && x < C) tile[threadIdx.y + i][threadIdx.x] = src[(size_t)y * C + x];
    }
    __syncthreads();
    int x2 = by + threadIdx.x;
    for (int i = 0; i < 32; i += 8) {
        int y2 = bx + threadIdx.y + i;
        if (y2 < C && x2 < R) dst[(size_t)y2 * R + x2] = tile[threadIdx.x][threadIdx.y + i];
    }
}

// ---------------- slot init ------------------------------------------------
__global__ void __launch_bounds__(256) copy_slots(const float* __restrict__ prev) {
    int i = blockIdx.x * 256 + threadIdx.x;
    g_slots[i] = prev[i];
}

// ---------------- q projection via folded M --------------------------------
// q~ = LN(g_slots) @ M, 6 independent accumulator chains per thread.
// Reads g_slots INTERNALLY (device symbol; never passed from host).
__global__ void __launch_bounds__(256) qproj2(const float* __restrict__ g_sw,
                                              const float* __restrict__ b_sw) {
    int idx = blockIdx.x;  // b*8+k
    int t = threadIdx.x;
    __shared__ float r1[256], r2[256], lnv[256];
    float x = g_slots[idx * D_ + t];
    r1[t] = x; r2[t] = x * x;
    __syncthreads();
    for (int o = 128; o; o >>= 1) {
        if (t < o) { r1[t] += r1[t + o]; r2[t] += r2[t + o]; }
        __syncthreads();
    }
    float mean = r1[0] * (1.f / 256.f);
    float var  = r2[0] * (1.f / 256.f) - mean * mean;
    float rstd = rsqrtf(var + 1e-5f);
    __syncthreads();
    lnv[t] = (x - mean) * rstd * g_sw[t] + b_sw[t];
    __syncthreads();

    float a00 = 0.f, a01 = 0.f, a10 = 0.f, a11 = 0.f, a20 = 0.f, a21 = 0.f;
#pragma unroll 4
    for (int d = 0; d < 256; d += 2) {
        float l0 = lnv[d], l1 = lnv[d + 1];
        const float* m0 = g_M + (size_t)d * 768;
        const float* m1 = m0 + 768;
        a00 += l0 * m0[t];       a01 += l1 * m1[t];
        a10 += l0 * m0[t + 256]; a11 += l1 * m1[t + 256];
        a20 += l0 * m0[t + 512]; a21 += l1 * m1[t + 512];
    }
    float* o = g_qt + (size_t)idx * F_;
    o[t] = a00 + a01; o[t + 256] = a10 + a11; o[t + 512] = a20 + a21;
}

// ---------------- fused attention pass -------------------------------------
// grid (NCHUNK=16, B=32), 256 threads.
// Phase 1 (token per thread): logits = q~ . fn * SCALE, softmax over 8 slots.
// Phase 2 (warp per 32-token group): U partials for all 8 slots; lanes = f-dims.
#define FCH 64                   // dims per tile chunk
#define NCH (F_ / FCH)           // 12
#define TROW 68                  // tile row stride (floats)
#define OFF_TILE 0
#define OFF_QT   (256 * TROW)                 // 17408 floats
#define OFF_RED  OFF_QT                       // overlay (phase2 only, 4096 floats)
#define OFF_ATT  (OFF_QT + K_ * F_)           // +6144
#define OFF_WS   (OFF_ATT + 256 * K_)         // +2048
#define SM_ATT_BYTES ((OFF_WS + 64) * 4)      // ~102.7 KB

__global__ void __launch_bounds__(256) fused_attn(float* __restrict__ attn_ext,
                                                  int final_pass) {
    extern __shared__ float sm[];
    int c = blockIdx.x, b = blockIdx.y;
    int t = threadIdx.x, w = t >> 5, lane = t & 31;
    float* tile = sm + OFF_TILE;
    float* qts  = sm + OFF_QT;
    float* red  = sm + OFF_RED;
    float* atT  = sm + OFF_ATT;
    float* ws   = sm + OFF_WS;

    // load q~ (8 x 768)
    const float4* qg = (const float4*)(g_qt + (size_t)b * K_ * F_);
#pragma unroll
    for (int i = 0; i < 6; i++) ((float4*)qts)[i * 256 + t] = qg[i * 256 + t];

    const float4* fg = (const float4*)(g_fn + ((size_t)(b * N_ + c * 256)) * F_);

    float acc[K_];
#pragma unroll
    for (int s = 0; s < K_; s++) acc[s] = 0.f;

    for (int ch = 0; ch < NCH; ch++) {
        __syncthreads();
#pragma unroll
        for (int i = 0; i < 16; i++) {
            int f = i * 256 + t;
            int r = f >> 4, dq = f & 15;
            float4 v = fg[(size_t)r * 192 + ch * 16 + dq];
            *(float4*)&tile[r * TROW + dq * 4] = v;
        }
        __syncthreads();
#pragma unroll
        for (int dq = 0; dq < 16; dq++) {
            float4 kv = *(float4*)&tile[t * TROW + dq * 4];
#pragma unroll
            for (int s = 0; s < K_; s++) {
                float4 qv = *(float4*)&qts[s * F_ + ch * FCH + dq * 4];
                acc[s] += kv.x * qv.x + kv.y * qv.y + kv.z * qv.z + kv.w * qv.w;
            }
        }
    }

    float mx = acc[0] * SCALE_;
#pragma unroll
    for (int s = 0; s < K_; s++) { acc[s] *= SCALE_; mx = fmaxf(mx, acc[s]); }
    float e[K_], den = 0.f;
#pragma unroll
    for (int s = 0; s < K_; s++) { e[s] = expf(acc[s] - mx); den += e[s]; }
    float inv = 1.f / den;
#pragma unroll
    for (int s = 0; s < K_; s++) e[s] *= inv;
    // transposed attn store: atT[tok][slot]
    *(float4*)&atT[t * K_]     = make_float4(e[0], e[1], e[2], e[3]);
    *(float4*)&atT[t * K_ + 4] = make_float4(e[4], e[5], e[6], e[7]);
    if (final_pass) {
        int n = c * 256 + t;
#pragma unroll
        for (int s = 0; s < K_; s++)
            attn_ext[((size_t)(b * K_ + s)) * N_ + n] = e[s];
    }
    // rowsum partials
#pragma unroll
    for (int s = 0; s < K_; s++) {
        float r = e[s];
#pragma unroll
        for (int off = 16; off; off >>= 1) r += __shfl_xor_sync(0xFFFFFFFFu, r, off);
        if (lane == 0) ws[w * K_ + s] = r;
    }
    __syncthreads();
    if (t < K_) {
        float smv = 0.f;
#pragma unroll
        for (int w2 = 0; w2 < 8; w2++) smv += ws[w2 * K_ + t];
        g_partial[(b * K_ + t) * NCHUNK + c] = smv;
    }

    if (!final_pass) {
        // phase 2: warp w owns tokens [w*32, w*32+32); lanes cover 64 f of chunk
        int wtok = w * 32;
        int sslot = t >> 5, f2 = (lane) * 2;  // for final reduce mapping
        for (int ch = 0; ch < NCH; ch++) {
            __syncthreads();
#pragma unroll
            for (int i = 0; i < 16; i++) {
                int f = i * 256 + t;
                int r = f >> 4, dq = f & 15;
                float4 v = fg[(size_t)r * 192 + ch * 16 + dq];
                *(float4*)&tile[r * TROW + dq * 4] = v;
            }
            __syncthreads();
            float u[16];
#pragma unroll
            for (int j = 0; j < 16; j++) u[j] = 0.f;
#pragma unroll 4
            for (int tk = 0; tk < 32; tk++) {
                int tok = wtok + tk;
                float2 fv = *(float2*)&tile[tok * TROW + lane * 2];
                float4 a0 = *(float4*)&atT[tok * K_];
                float4 a1 = *(float4*)&atT[tok * K_ + 4];
                u[0] += a0.x * fv.x;  u[1] += a0.x * fv.y;
                u[2] += a0.y * fv.x;  u[3] += a0.y * fv.y;
                u[4] += a0.z * fv.x;  u[5] += a0.z * fv.y;
                u[6] += a0.w * fv.x;  u[7] += a0.w * fv.y;
                u[8] += a1.x * fv.x;  u[9] += a1.x * fv.y;
                u[10] += a1.y * fv.x; u[11] += a1.y * fv.y;
                u[12] += a1.z * fv.x; u[13] += a1.z * fv.y;
                u[14] += a1.w * fv.x; u[15] += a1.w * fv.y;
            }
            // per-warp partials -> red[w][s][64]
#pragma unroll
            for (int s = 0; s < K_; s++)
                *(float2*)&red[(w * K_ + s) * FCH + lane * 2] = make_float2(u[2 * s], u[2 * s + 1]);
            __syncthreads();
            // cross-warp reduce: thread -> (slot = t>>5, f pair = lane*2)
            float r0 = 0.f, r1v = 0.f;
#pragma unroll
            for (int w2 = 0; w2 < 8; w2++) {
                float2 p = *(float2*)&red[(w2 * K_ + sslot) * FCH + f2];
                r0 += p.x; r1v += p.y;
            }
            float* up = g_upart + ((size_t)((b * NCHUNK + c) * K_ + sslot)) * F_ + ch * FCH + f2;
            *(float2*)up = make_float2(r0, r1v);
        }
    }
}

// ---------------- deterministic row-sum reduce -----------------------------
__global__ void __launch_bounds__(256) rowsum_reduce() {
    int t = threadIdx.x;  // 256 = B*K
    float s = 0.f;
#pragma unroll
    for (int c = 0; c < NCHUNK; c++) s += g_partial[t * NCHUNK + c];
    g_rowsum[t] = s;
}

// ---------------- U reduce + Wv fold + GRU + LN + MLP (per slot) -----------
__global__ void __launch_bounds__(256) gru_mlp(const float* __restrict__ b_ih,
                                               const float* __restrict__ b_hh,
                                               const float* __restrict__ g_mw,
                                               const float* __restrict__ b_mw,
                                               const float* __restrict__ b1,
                                               const float* __restrict__ b2) {
    int idx = blockIdx.x;  // b*8+k
    int b = idx >> 3, k = idx & 7;
    int t = threadIdx.x;
    __shared__ float us[768];
    __shared__ float upd[256], slt[256], lnbuf[256], mbuf[256], r1[256], r2[256];

#pragma unroll
    for (int j = 0; j < 3; j++) {
        int f = t + 256 * j;
        float s = 0.f;
#pragma unroll
        for (int c = 0; c < NCHUNK; c++)
            s += g_upart[((size_t)((b * NCHUNK + c) * K_ + k)) * F_ + f];
        us[f] = s;
    }
    float sv = g_slots[idx * D_ + t];
    slt[t] = sv;
    __syncthreads();

    float invr = 1.f / (g_rowsum[idx] + EPS_);
    float a = 0.f;
#pragma unroll 8
    for (int f = 0; f < 768; f++) a += us[f] * g_WvT[f * 256 + t];
    upd[t] = a * invr;
    __syncthreads();

    float gir = b_ih[t], giz = b_ih[256 + t], gin = b_ih[512 + t];
    float ghr = b_hh[t], ghz = b_hh[256 + t], ghn = b_hh[512 + t];
#pragma unroll 4
    for (int d = 0; d < 256; d++) {
        float ud = upd[d], sd = slt[d];
        const float* wi = &g_WihT[d * 768];
        const float* wh = &g_WhhT[d * 768];
        gir += ud * wi[t];       ghr += sd * wh[t];
        giz += ud * wi[256 + t]; ghz += sd * wh[256 + t];
        gin += ud * wi[512 + t]; ghn += sd * wh[512 + t];
    }
    float r = 1.f / (1.f + expf(-(gir + ghr)));
    float z = 1.f / (1.f + expf(-(giz + ghz)));
    float nn = tanhf(gin + r * ghn);
    float h = (1.f - z) * nn + z * sv;

    r1[t] = h; r2[t] = h * h;
    __syncthreads();
    for (int o = 128; o; o >>= 1) {
        if (t < o) { r1[t] += r1[t + o]; r2[t] += r2[t + o]; }
        __syncthreads();
    }
    float mean = r1[0] * (1.f / 256.f);
    float var  = r2[0] * (1.f / 256.f) - mean * mean;
    float rstd = rsqrtf(var + 1e-5f);
    __syncthreads();
    lnbuf[t] = (h - mean) * rstd * g_mw[t] + b_mw[t];
    __syncthreads();

    float acc = b1[t];
#pragma unroll 8
    for (int d = 0; d < 256; d++) acc += lnbuf[d] * g_W1T[d * 256 + t];
    mbuf[t] = fmaxf(acc, 0.f);
    __syncthreads();

    float o = h + b2[t];
#pragma unroll 8
    for (int j = 0; j < 256; j++) o += mbuf[j] * g_W2T[j * 256 + t];
    g_slots[idx * D_ + t] = o;
}

// ---------------- final confidence blend -----------------------------------
__global__ void __launch_bounds__(256) blend(const float* __restrict__ prev,
                                             float* __restrict__ out_slots) {
    int idx = blockIdx.x;  // b*8+k
    int t = threadIdx.x;
    float mask = 1.f / (1.f + expf(-g_rowsum[idx] * (1.f / (float)N_)));
    out_slots[idx * D_ + t] =
        g_slots[idx * D_ + t] * mask + prev[idx * D_ + t] * (1.f - mask);
}

// ---------------- launch ----------------------------------------------------
extern "C" void kernel_launch(void* const* d_in, const int* in_sizes, int n_in,
                              void* d_out, int out_size) {
    const float* features = (const float*)d_in[0];
    const float* prev_slots = (const float*)d_in[1];
    const float* gin  = (const float*)d_in[2];
    const float* bin  = (const float*)d_in[3];
    const float* g_sw = (const float*)d_in[4];
    const float* b_sw = (const float*)d_in[5];
    const float* g_mw = (const float*)d_in[6];
    const float* b_mw = (const float*)d_in[7];
    const float* Wq   = (const float*)d_in[8];
    const float* Wk   = (const float*)d_in[9];
    const float* Wv   = (const float*)d_in[10];
    const float* W_ih = (const float*)d_in[11];
    const float* W_hh = (const float*)d_in[12];
    const float* b_ih = (const float*)d_in[13];
    const float* b_hh = (const float*)d_in[14];
    const float* W1   = (const float*)d_in[15];
    const float* b1   = (const float*)d_in[16];
    const float* W2   = (const float*)d_in[17];
    const float* b2   = (const float*)d_in[18];

    float* out = (float*)d_out;
    float* out_slots = out;                       // (B, K, 256)
    float* out_attn  = out + B_ * K_ * D_;        // (B, K, N)

    cudaFuncSetAttribute(fused_attn, cudaFuncAttributeMaxDynamicSharedMemorySize,
                         SM_ATT_BYTES);

    // R15 launch-order skeleton (known good), tWq+qproj_fold -> make_M+qproj2
    ln_conv<<<NB_, 256>>>(features, gin, bin);                               // 0
    copy_slots<<<(B_ * K_ * D_) / 256, 256>>>(prev_slots);                   // 1
    make_M<<<256, 256>>>(Wq, Wk);                                            // 2
    qproj2<<<B_ * K_, 256>>>(g_sw, b_sw);                                    // 3
    transpose_k<<<dim3(768 / 32, 256 / 32), dim3(32, 8)>>>(Wv, 256, 768, 5); // 4
    fused_attn<<<dim3(NCHUNK, B_), 256, SM_ATT_BYTES>>>(out_attn, 0);        // 5
    transpose_k<<<dim3(256 / 32, 768 / 32), dim3(32, 8)>>>(W_ih, 768, 256, 0);
    transpose_k<<<dim3(256 / 32, 768 / 32), dim3(32, 8)>>>(W_hh, 768, 256, 1);
    transpose_k<<<dim3(256 / 32, 256 / 32), dim3(32, 8)>>>(W1, 256, 256, 2);
    transpose_k<<<dim3(256 / 32, 256 / 32), dim3(32, 8)>>>(W2, 256, 256, 3);
    rowsum_reduce<<<1, 256>>>();
    gru_mlp<<<B_ * K_, 256>>>(b_ih, b_hh, g_mw, b_mw, b1, b2);

    for (int it = 1; it < 3; it++) {
        qproj2<<<B_ * K_, 256>>>(g_sw, b_sw);
        fused_attn<<<dim3(NCHUNK, B_), 256, SM_ATT_BYTES>>>(out_attn, 0);
        rowsum_reduce<<<1, 256>>>();
        gru_mlp<<<B_ * K_, 256>>>(b_ih, b_hh, g_mw, b_mw, b1, b2);
    }

    qproj2<<<B_ * K_, 256>>>(g_sw, b_sw);
    fused_attn<<<dim3(NCHUNK, B_), 256, SM_ATT_BYTES>>>(out_attn, 1);
    rowsum_reduce<<<1, 256>>>();
    blend<<<B_ * K_, 256>>>(prev_slots, out_slots);
}